// round 12
// baseline (speedup 1.0000x reference)
#include <cuda_runtime.h>
#include <math.h>
#include <stdint.h>

#define A_N 49104
#define B_N 8
#define C_N 80
#define K_N 256
#define IMG 512.0f
#define ROW4 20                 // 80 floats = 20 float4 per anchor
#define CH 1024                 // anchors per chunk
#define NCH 48                  // chunks per batch (48*1024 >= 49104)

typedef unsigned long long u64;

// -------- device scratch --------
__device__ u64 g_cand[B_N * NCH * K_N];   // chunk top-256 lists

// ============================================================
// warp-level compare-exchange helpers (descending networks)
// ============================================================
__device__ __forceinline__ void cx_reg(u64& a, u64& b, bool desc) {
    u64 lo = (a < b) ? a : b;
    u64 hi = (a < b) ? b : a;
    a = desc ? hi : lo;
    b = desc ? lo : hi;
}
__device__ __forceinline__ u64 cx_shfl(u64 v, int j, bool desc, int lane) {
    u64 pv = __shfl_xor_sync(0xffffffffu, v, j);
    bool lower = (lane & j) == 0;
    bool keepmax = (desc == lower);
    u64 mx = (v > pv) ? v : pv;
    u64 mn = (v > pv) ? pv : v;
    return keepmax ? mx : mn;
}

// clean a 256-elem bitonic sequence (8 regs/lane, e = r*32+lane) to descending
__device__ __forceinline__ void clean256(u64 a[8], int lane) {
    cx_reg(a[0], a[4], true); cx_reg(a[1], a[5], true);
    cx_reg(a[2], a[6], true); cx_reg(a[3], a[7], true);
    cx_reg(a[0], a[2], true); cx_reg(a[1], a[3], true);
    cx_reg(a[4], a[6], true); cx_reg(a[5], a[7], true);
    cx_reg(a[0], a[1], true); cx_reg(a[2], a[3], true);
    cx_reg(a[4], a[5], true); cx_reg(a[6], a[7], true);
#pragma unroll
    for (int j = 16; j >= 1; j >>= 1)
#pragma unroll
        for (int r = 0; r < 8; r++) a[r] = cx_shfl(a[r], j, true, lane);
}

// clean a 128-elem bitonic sequence (4 regs/lane) to descending
__device__ __forceinline__ void clean128(u64 a[4], int lane) {
    cx_reg(a[0], a[2], true); cx_reg(a[1], a[3], true);
    cx_reg(a[0], a[1], true); cx_reg(a[2], a[3], true);
#pragma unroll
    for (int j = 16; j >= 1; j >>= 1)
#pragma unroll
        for (int r = 0; r < 4; r++) a[r] = cx_shfl(a[r], j, true, lane);
}

// ============================================================
// K1: fused score + chunk top-256 (unchanged from R11).
// ============================================================
__global__ __launch_bounds__(512) void k_topk_local(const float* __restrict__ cls) {
    __shared__ u64 sk[CH];
    const int tid = threadIdx.x;
    const int lane = tid & 31;
    const int w = tid >> 5;                 // warp 0..15
    const int b = blockIdx.x / NCH;
    const int c = blockIdx.x % NCH;
    const int base = c * CH + w * 64;
    const float4* cls4 = reinterpret_cast<const float4*>(cls) + (size_t)b * A_N * ROW4;

    const int j = lane & 3;
#pragma unroll
    for (int it = 0; it < 8; it++) {
        int al = it * 8 + (lane >> 2);
        int a = base + al;
        float m = -INFINITY;
        if (a < A_N) {
            const float4* row = cls4 + (size_t)a * ROW4 + j;
            float4 v0 = row[0];
            float4 v1 = row[4];
            float4 v2 = row[8];
            float4 v3 = row[12];
            float4 v4 = row[16];
            m = fmaxf(fmaxf(fmaxf(v0.x, v0.y), fmaxf(v0.z, v0.w)),
                fmaxf(fmaxf(fmaxf(v1.x, v1.y), fmaxf(v1.z, v1.w)),
                fmaxf(fmaxf(fmaxf(v2.x, v2.y), fmaxf(v2.z, v2.w)),
                fmaxf(fmaxf(fmaxf(v3.x, v3.y), fmaxf(v3.z, v3.w)),
                      fmaxf(fmaxf(v4.x, v4.y), fmaxf(v4.z, v4.w))))));
        }
        m = fmaxf(m, __shfl_xor_sync(0xffffffffu, m, 1));
        m = fmaxf(m, __shfl_xor_sync(0xffffffffu, m, 2));
        if (j == 0) {
            u64 key = 0ull;
            if (a < A_N) {
                float score = 1.0f / (1.0f + expf(-m));
                if (!(score > 0.01f)) score = 0.0f;
                key = ((u64)__float_as_uint(score) << 32) |
                      (u64)(0xFFFFFFFFu - (unsigned)a);
            }
            sk[w * 64 + al] = key;
        }
    }
    __syncwarp();

    // warp register sort of 64 keys (descending)
    {
        u64 v[2];
        v[0] = sk[w * 64 + lane];
        v[1] = sk[w * 64 + 32 + lane];
        for (int k = 2; k <= 64; k <<= 1) {
            for (int jj = k >> 1; jj >= 1; jj >>= 1) {
                if (jj >= 32) {
                    cx_reg(v[0], v[1], true);
                } else {
#pragma unroll
                    for (int r = 0; r < 2; r++) {
                        bool desc = (k >= 32) ? (((r * 32) & k) == 0)
                                              : ((lane & k) == 0);
                        v[r] = cx_shfl(v[r], jj, desc, lane);
                    }
                }
            }
        }
        sk[w * 64 + lane] = v[0];
        sk[w * 64 + 32 + lane] = v[1];
    }
    __syncthreads();

    // L1: 8 warps, full merge two 64-lists -> sorted 128
    if (w < 8) {
        int bs = w * 128;
        u64 a[4];
        a[0] = sk[bs + lane];
        a[1] = sk[bs + 32 + lane];
        a[2] = sk[bs + 64 + (63 - lane)];
        a[3] = sk[bs + 64 + (31 - lane)];
        __syncwarp();
        clean128(a, lane);
        sk[bs + lane] = a[0];
        sk[bs + 32 + lane] = a[1];
        sk[bs + 64 + lane] = a[2];
        sk[bs + 96 + lane] = a[3];
    }
    __syncthreads();

    // L2: 4 warps, full merge two 128-lists -> sorted 256
    if (w < 4) {
        int bs = w * 256;
        u64 a[8];
#pragma unroll
        for (int r = 0; r < 4; r++) a[r] = sk[bs + r * 32 + lane];
#pragma unroll
        for (int r = 4; r < 8; r++) a[r] = sk[bs + 383 - r * 32 - lane];
        __syncwarp();
        clean256(a, lane);
#pragma unroll
        for (int r = 0; r < 8; r++) sk[bs + r * 32 + lane] = a[r];
    }
    __syncthreads();

    // L3: 2 warps, truncating merge 256+256 -> top-256
    if (w < 2) {
        int A0 = w * 512;
        u64 a[8];
#pragma unroll
        for (int r = 0; r < 8; r++) {
            int e = r * 32 + lane;
            u64 x = sk[A0 + e];
            u64 y = sk[A0 + 256 + 255 - e];
            a[r] = (x > y) ? x : y;
        }
        __syncwarp();
        clean256(a, lane);
#pragma unroll
        for (int r = 0; r < 8; r++) sk[A0 + r * 32 + lane] = a[r];
    }
    __syncthreads();

    // L4: 1 warp, truncating merge -> final top-256 -> global
    if (w == 0) {
        u64 a[8];
#pragma unroll
        for (int r = 0; r < 8; r++) {
            int e = r * 32 + lane;
            u64 x = sk[e];
            u64 y = sk[512 + 255 - e];
            a[r] = (x > y) ? x : y;
        }
        clean256(a, lane);
#pragma unroll
        for (int r = 0; r < 8; r++)
            g_cand[blockIdx.x * K_N + r * 32 + lane] = a[r];
    }
}

// ============================================================
// K2: fused merge(48 lists) + gather/decode + word-seq NMS + out.
// ============================================================
extern __shared__ u64 sh[];

__global__ __launch_bounds__(1024) void k_final(const float* __restrict__ cls,
                                                const float* __restrict__ regs,
                                                const float* __restrict__ anchors,
                                                float* __restrict__ out,
                                                int out_size) {
    const int b = blockIdx.x;
    const int tid = threadIdx.x;
    const int lane = tid & 31;
    const int w = tid >> 5;                 // warp 0..31

    u64* lists = sh;                                        // 24 * 256 u64 peak
    float4*   bx  = reinterpret_cast<float4*>(sh + 256);
    float*    sc  = reinterpret_cast<float*>(sh + 768);
    int*      lb  = reinterpret_cast<int*>(sh + 896);
    unsigned* msk = reinterpret_cast<unsigned*>(sh + 1024); // 256*8 words
    __shared__ unsigned keepw[8];

    u64 a[8];

    // ---- stage 1: 24 warps: trunc-merge g_cand pairs -> lists[w] ----
    if (w < 24) {
        const u64* A = g_cand + ((size_t)(b * NCH + 2 * w)) * K_N;
        const u64* B = A + K_N;
#pragma unroll
        for (int r = 0; r < 8; r++) {
            int e = r * 32 + lane;
            u64 x = A[e], y = B[255 - e];
            a[r] = (x > y) ? x : y;
        }
        clean256(a, lane);
#pragma unroll
        for (int r = 0; r < 8; r++) lists[w * 256 + r * 32 + lane] = a[r];
    }
    __syncthreads();

    // ---- stages 2-4: 12, 6, 3 active warps ----
#pragma unroll
    for (int npair = 12; npair >= 3; npair >>= 1) {
        if (w < npair) {
#pragma unroll
            for (int r = 0; r < 8; r++) {
                int e = r * 32 + lane;
                u64 x = lists[2 * w * 256 + e];
                u64 y = lists[(2 * w + 1) * 256 + 255 - e];
                a[r] = (x > y) ? x : y;
            }
        }
        __syncthreads();
        if (w < npair) {
            clean256(a, lane);
#pragma unroll
            for (int r = 0; r < 8; r++) lists[w * 256 + r * 32 + lane] = a[r];
        }
        __syncthreads();
    }

    // ---- final: warp 0 chains lists 0,1 then 2 ----
    if (w == 0) {
#pragma unroll
        for (int r = 0; r < 8; r++) {
            int e = r * 32 + lane;
            u64 x = lists[e];
            u64 y = lists[256 + 255 - e];
            a[r] = (x > y) ? x : y;
        }
        clean256(a, lane);
#pragma unroll
        for (int r = 0; r < 8; r++) {
            int e = r * 32 + lane;
            u64 y = lists[512 + 255 - e];
            if (y > a[r]) a[r] = y;
        }
        clean256(a, lane);
        __syncwarp();
#pragma unroll
        for (int r = 0; r < 8; r++) lists[r * 32 + lane] = a[r];
    }
    __syncthreads();
    // lists[0..255] = exact top-256 (score desc, idx asc)

    // ---- gather: 4 threads per winner; j==0 decodes box ----
    {
        int e = tid >> 2, j = tid & 3;
        u64 v = lists[e];
        unsigned kbits = (unsigned)(v >> 32);
        unsigned aidx = 0xFFFFFFFFu - (unsigned)(v & 0xFFFFFFFFu);
        const float4* row = reinterpret_cast<const float4*>(cls) +
                            ((size_t)b * A_N + aidx) * ROW4;
        float m = -INFINITY;
        int arg = 0;
#pragma unroll
        for (int q0 = 0; q0 < 5; q0++) {
            int q = j + 4 * q0;
            float4 x = row[q];
            int cc = 4 * q;
            if (x.x > m) { m = x.x; arg = cc; }
            if (x.y > m) { m = x.y; arg = cc + 1; }
            if (x.z > m) { m = x.z; arg = cc + 2; }
            if (x.w > m) { m = x.w; arg = cc + 3; }
        }
#pragma unroll
        for (int off = 1; off < 4; off <<= 1) {
            float mo = __shfl_xor_sync(0xffffffffu, m, off);
            int ao = __shfl_xor_sync(0xffffffffu, arg, off);
            if (mo > m || (mo == m && ao < arg)) { m = mo; arg = ao; }
        }
        if (j == 0) {
            sc[e] = __uint_as_float(kbits);
            lb[e] = arg;
            float4 an = reinterpret_cast<const float4*>(anchors)[aidx];
            float aw = an.z - an.x, ah = an.w - an.y;
            float acx = an.x + 0.5f * aw, acy = an.y + 0.5f * ah;
            float4 rg = reinterpret_cast<const float4*>(regs)[(size_t)b * A_N + aidx];
            float cx = acx + rg.x * aw;
            float cy = acy + rg.y * ah;
            float dw = fminf(fmaxf(rg.z, -4.0f), 4.0f);
            float dh = fminf(fmaxf(rg.w, -4.0f), 4.0f);
            float ww = aw * expf(dw);
            float hh = ah * expf(dh);
            float x1 = fminf(fmaxf(cx - 0.5f * ww, 0.0f), IMG);
            float y1 = fminf(fmaxf(cy - 0.5f * hh, 0.0f), IMG);
            float x2 = fminf(fmaxf(cx + 0.5f * ww, 0.0f), IMG);
            float y2 = fminf(fmaxf(cy + 0.5f * hh, 0.0f), IMG);
            bx[e] = make_float4(x1, y1, x2, y2);
        }
    }
    __syncthreads();

    // ---- NMS masks: 4 threads per candidate, 64 columns each ----
    {
        int i = tid >> 2, q = tid & 3;
        float4 me = bx[i];
        float myarea = fmaxf(me.z - me.x, 0.0f) * fmaxf(me.w - me.y, 0.0f);
        unsigned w0 = 0u, w1 = 0u;
        int j0 = q * 64;
#pragma unroll 4
        for (int jj = 0; jj < 64; jj++) {
            float4 o = bx[j0 + jj];
            float ix1 = fmaxf(me.x, o.x);
            float iy1 = fmaxf(me.y, o.y);
            float ix2 = fminf(me.z, o.z);
            float iy2 = fminf(me.w, o.w);
            float iw = fmaxf(ix2 - ix1, 0.0f);
            float ih = fmaxf(iy2 - iy1, 0.0f);
            float inter = iw * ih;
            float oarea = fmaxf(o.z - o.x, 0.0f) * fmaxf(o.w - o.y, 0.0f);
            float uni = myarea + oarea - inter;
            float iou = inter / fmaxf(uni, 1e-8f);
            if (iou > 0.5f) {
                if (jj < 32) w0 |= 1u << jj;
                else w1 |= 1u << (jj - 32);
            }
        }
        msk[i * 8 + q * 2 + 0] = w0;
        msk[i * 8 + q * 2 + 1] = w1;
    }
    __syncthreads();

    // ---- exact word-sequential NMS in ONE warp ----
    // 8 outer steps (32 candidates each). Lane i owns candidate
    // word*32+i. External suppression from finalized earlier words
    // is pure register work; intra-word order resolved by ffs/ballot
    // loop (<=32 cheap register iterations, no LDS inside).
    if (w == 0) {
        unsigned fin[8];
#pragma unroll
        for (int v = 0; v < 8; v++) fin[v] = 0u;
        for (int word = 0; word < 8; word++) {
            int c = word * 32 + lane;
            unsigned mw[8];
#pragma unroll
            for (int v = 0; v < 8; v++) mw[v] = msk[c * 8 + v];
            bool ok = sc[c] > 0.0f;
            unsigned supext = 0u;
#pragma unroll
            for (int v = 0; v < 8; v++)
                if (v < word) supext |= mw[v] & fin[v];
            unsigned cand = __ballot_sync(0xffffffffu, ok && supext == 0u);
            unsigned keep = 0u;
            while (cand) {
                int bpos = __ffs(cand) - 1;
                keep |= 1u << bpos;
                unsigned m = __shfl_sync(0xffffffffu, mw[word], bpos);
                cand &= ~m;
                cand &= ~(1u << bpos);
            }
            fin[word] = keep;
        }
        if (lane < 8) keepw[lane] = fin[lane];
    }
    __syncthreads();

    // ---- output ----
    if (tid < K_N) {
        bool kp = (keepw[tid >> 5] >> (tid & 31)) & 1u;
        float kf = kp ? 1.0f : 0.0f;
        int base = b * K_N + tid;
        float4 me = bx[tid];
        out[base * 5 + 0] = me.x * kf;
        out[base * 5 + 1] = me.y * kf;
        out[base * 5 + 2] = me.z * kf;
        out[base * 5 + 3] = me.w * kf;
        out[base * 5 + 4] = sc[tid] * kf;
        if (out_size >= B_N * K_N * 5 + B_N * K_N)
            out[B_N * K_N * 5 + base] = (float)lb[tid];
        if (out_size >= B_N * K_N * 5 + 2 * B_N * K_N)
            out[B_N * K_N * 5 + B_N * K_N + base] = kf;
    }
}

// ============================================================
extern "C" void kernel_launch(void* const* d_in, const int* in_sizes, int n_in,
                              void* d_out, int out_size) {
    const float* cls = nullptr;
    const float* regs = nullptr;
    const float* anchors = nullptr;
    for (int i = 0; i < n_in; i++) {
        if (in_sizes[i] == B_N * A_N * C_N) cls = (const float*)d_in[i];
        else if (in_sizes[i] == B_N * A_N * 4) regs = (const float*)d_in[i];
        else if (in_sizes[i] == A_N * 4) anchors = (const float*)d_in[i];
    }
    if (!cls || !regs || !anchors) return;

    float* out = (float*)d_out;

    const int SMEM_K2 = 24 * 256 * sizeof(u64);   // 49152 bytes
    cudaFuncSetAttribute(k_final, cudaFuncAttributeMaxDynamicSharedMemorySize, SMEM_K2);

    k_topk_local<<<B_N * NCH, 512>>>(cls);
    k_final<<<B_N, 1024, SMEM_K2>>>(cls, regs, anchors, out, out_size);
}

// round 13
// speedup vs baseline: 1.1745x; 1.1745x over previous
#include <cuda_runtime.h>
#include <math.h>
#include <stdint.h>

#define A_N 49104
#define B_N 8
#define C_N 80
#define K_N 256
#define IMG 512.0f
#define ROW4 20                 // 80 floats = 20 float4 per anchor
#define CH 1024                 // anchors per chunk
#define NCH 48                  // chunks per batch (48*1024 >= 49104)

typedef unsigned long long u64;

// -------- device scratch --------
__device__ u64 g_cand[B_N * NCH * K_N];   // chunk top-256 lists

// ============================================================
// warp-level compare-exchange helpers (descending networks)
// ============================================================
__device__ __forceinline__ void cx_reg(u64& a, u64& b, bool desc) {
    u64 lo = (a < b) ? a : b;
    u64 hi = (a < b) ? b : a;
    a = desc ? hi : lo;
    b = desc ? lo : hi;
}
__device__ __forceinline__ u64 cx_shfl(u64 v, int j, bool desc, int lane) {
    u64 pv = __shfl_xor_sync(0xffffffffu, v, j);
    bool lower = (lane & j) == 0;
    bool keepmax = (desc == lower);
    u64 mx = (v > pv) ? v : pv;
    u64 mn = (v > pv) ? pv : v;
    return keepmax ? mx : mn;
}

// clean a 256-elem bitonic sequence (8 regs/lane, e = r*32+lane) to descending
__device__ __forceinline__ void clean256(u64 a[8], int lane) {
    cx_reg(a[0], a[4], true); cx_reg(a[1], a[5], true);
    cx_reg(a[2], a[6], true); cx_reg(a[3], a[7], true);
    cx_reg(a[0], a[2], true); cx_reg(a[1], a[3], true);
    cx_reg(a[4], a[6], true); cx_reg(a[5], a[7], true);
    cx_reg(a[0], a[1], true); cx_reg(a[2], a[3], true);
    cx_reg(a[4], a[5], true); cx_reg(a[6], a[7], true);
#pragma unroll
    for (int j = 16; j >= 1; j >>= 1)
#pragma unroll
        for (int r = 0; r < 8; r++) a[r] = cx_shfl(a[r], j, true, lane);
}

// clean a 128-elem bitonic sequence (4 regs/lane) to descending
__device__ __forceinline__ void clean128(u64 a[4], int lane) {
    cx_reg(a[0], a[2], true); cx_reg(a[1], a[3], true);
    cx_reg(a[0], a[1], true); cx_reg(a[2], a[3], true);
#pragma unroll
    for (int j = 16; j >= 1; j >>= 1)
#pragma unroll
        for (int r = 0; r < 4; r++) a[r] = cx_shfl(a[r], j, true, lane);
}

// ============================================================
// K1: fused score + chunk top-256 (unchanged from R11).
// ============================================================
__global__ __launch_bounds__(512) void k_topk_local(const float* __restrict__ cls) {
    __shared__ u64 sk[CH];
    const int tid = threadIdx.x;
    const int lane = tid & 31;
    const int w = tid >> 5;                 // warp 0..15
    const int b = blockIdx.x / NCH;
    const int c = blockIdx.x % NCH;
    const int base = c * CH + w * 64;
    const float4* cls4 = reinterpret_cast<const float4*>(cls) + (size_t)b * A_N * ROW4;

    const int j = lane & 3;
#pragma unroll
    for (int it = 0; it < 8; it++) {
        int al = it * 8 + (lane >> 2);
        int a = base + al;
        float m = -INFINITY;
        if (a < A_N) {
            const float4* row = cls4 + (size_t)a * ROW4 + j;
            float4 v0 = row[0];
            float4 v1 = row[4];
            float4 v2 = row[8];
            float4 v3 = row[12];
            float4 v4 = row[16];
            m = fmaxf(fmaxf(fmaxf(v0.x, v0.y), fmaxf(v0.z, v0.w)),
                fmaxf(fmaxf(fmaxf(v1.x, v1.y), fmaxf(v1.z, v1.w)),
                fmaxf(fmaxf(fmaxf(v2.x, v2.y), fmaxf(v2.z, v2.w)),
                fmaxf(fmaxf(fmaxf(v3.x, v3.y), fmaxf(v3.z, v3.w)),
                      fmaxf(fmaxf(v4.x, v4.y), fmaxf(v4.z, v4.w))))));
        }
        m = fmaxf(m, __shfl_xor_sync(0xffffffffu, m, 1));
        m = fmaxf(m, __shfl_xor_sync(0xffffffffu, m, 2));
        if (j == 0) {
            u64 key = 0ull;
            if (a < A_N) {
                float score = 1.0f / (1.0f + expf(-m));
                if (!(score > 0.01f)) score = 0.0f;
                key = ((u64)__float_as_uint(score) << 32) |
                      (u64)(0xFFFFFFFFu - (unsigned)a);
            }
            sk[w * 64 + al] = key;
        }
    }
    __syncwarp();

    // warp register sort of 64 keys (descending)
    {
        u64 v[2];
        v[0] = sk[w * 64 + lane];
        v[1] = sk[w * 64 + 32 + lane];
        for (int k = 2; k <= 64; k <<= 1) {
            for (int jj = k >> 1; jj >= 1; jj >>= 1) {
                if (jj >= 32) {
                    cx_reg(v[0], v[1], true);
                } else {
#pragma unroll
                    for (int r = 0; r < 2; r++) {
                        bool desc = (k >= 32) ? (((r * 32) & k) == 0)
                                              : ((lane & k) == 0);
                        v[r] = cx_shfl(v[r], jj, desc, lane);
                    }
                }
            }
        }
        sk[w * 64 + lane] = v[0];
        sk[w * 64 + 32 + lane] = v[1];
    }
    __syncthreads();

    // L1: 8 warps, full merge two 64-lists -> sorted 128
    if (w < 8) {
        int bs = w * 128;
        u64 a[4];
        a[0] = sk[bs + lane];
        a[1] = sk[bs + 32 + lane];
        a[2] = sk[bs + 64 + (63 - lane)];
        a[3] = sk[bs + 64 + (31 - lane)];
        __syncwarp();
        clean128(a, lane);
        sk[bs + lane] = a[0];
        sk[bs + 32 + lane] = a[1];
        sk[bs + 64 + lane] = a[2];
        sk[bs + 96 + lane] = a[3];
    }
    __syncthreads();

    // L2: 4 warps, full merge two 128-lists -> sorted 256
    if (w < 4) {
        int bs = w * 256;
        u64 a[8];
#pragma unroll
        for (int r = 0; r < 4; r++) a[r] = sk[bs + r * 32 + lane];
#pragma unroll
        for (int r = 4; r < 8; r++) a[r] = sk[bs + 383 - r * 32 - lane];
        __syncwarp();
        clean256(a, lane);
#pragma unroll
        for (int r = 0; r < 8; r++) sk[bs + r * 32 + lane] = a[r];
    }
    __syncthreads();

    // L3: 2 warps, truncating merge 256+256 -> top-256
    if (w < 2) {
        int A0 = w * 512;
        u64 a[8];
#pragma unroll
        for (int r = 0; r < 8; r++) {
            int e = r * 32 + lane;
            u64 x = sk[A0 + e];
            u64 y = sk[A0 + 256 + 255 - e];
            a[r] = (x > y) ? x : y;
        }
        __syncwarp();
        clean256(a, lane);
#pragma unroll
        for (int r = 0; r < 8; r++) sk[A0 + r * 32 + lane] = a[r];
    }
    __syncthreads();

    // L4: 1 warp, truncating merge -> final top-256 -> global
    if (w == 0) {
        u64 a[8];
#pragma unroll
        for (int r = 0; r < 8; r++) {
            int e = r * 32 + lane;
            u64 x = sk[e];
            u64 y = sk[512 + 255 - e];
            a[r] = (x > y) ? x : y;
        }
        clean256(a, lane);
#pragma unroll
        for (int r = 0; r < 8; r++)
            g_cand[blockIdx.x * K_N + r * 32 + lane] = a[r];
    }
}

// ============================================================
// K2: fused merge(48 lists) + gather/decode + NMS + out.
// ============================================================
extern __shared__ u64 sh[];

__global__ __launch_bounds__(1024) void k_final(const float* __restrict__ cls,
                                                const float* __restrict__ regs,
                                                const float* __restrict__ anchors,
                                                float* __restrict__ out,
                                                int out_size) {
    const int b = blockIdx.x;
    const int tid = threadIdx.x;
    const int lane = tid & 31;
    const int w = tid >> 5;                 // warp 0..31

    u64* lists = sh;                                        // 24 * 256 u64 peak
    float4*   bx  = reinterpret_cast<float4*>(sh + 256);
    float*    sc  = reinterpret_cast<float*>(sh + 768);
    int*      lb  = reinterpret_cast<int*>(sh + 896);
    unsigned* msk = reinterpret_cast<unsigned*>(sh + 1024); // 256*8 words
    __shared__ unsigned keepw[8];

    u64 a[8];

    // ---- stage 1: 24 warps: trunc-merge g_cand pairs -> lists[w] ----
    if (w < 24) {
        const u64* A = g_cand + ((size_t)(b * NCH + 2 * w)) * K_N;
        const u64* B = A + K_N;
#pragma unroll
        for (int r = 0; r < 8; r++) {
            int e = r * 32 + lane;
            u64 x = A[e], y = B[255 - e];
            a[r] = (x > y) ? x : y;
        }
        clean256(a, lane);
#pragma unroll
        for (int r = 0; r < 8; r++) lists[w * 256 + r * 32 + lane] = a[r];
    }
    __syncthreads();

    // ---- stages 2-4: 12, 6, 3 active warps ----
#pragma unroll
    for (int npair = 12; npair >= 3; npair >>= 1) {
        if (w < npair) {
#pragma unroll
            for (int r = 0; r < 8; r++) {
                int e = r * 32 + lane;
                u64 x = lists[2 * w * 256 + e];
                u64 y = lists[(2 * w + 1) * 256 + 255 - e];
                a[r] = (x > y) ? x : y;
            }
        }
        __syncthreads();
        if (w < npair) {
            clean256(a, lane);
#pragma unroll
            for (int r = 0; r < 8; r++) lists[w * 256 + r * 32 + lane] = a[r];
        }
        __syncthreads();
    }

    // ---- final: warp 0 chains lists 0,1 then 2 ----
    if (w == 0) {
#pragma unroll
        for (int r = 0; r < 8; r++) {
            int e = r * 32 + lane;
            u64 x = lists[e];
            u64 y = lists[256 + 255 - e];
            a[r] = (x > y) ? x : y;
        }
        clean256(a, lane);
#pragma unroll
        for (int r = 0; r < 8; r++) {
            int e = r * 32 + lane;
            u64 y = lists[512 + 255 - e];
            if (y > a[r]) a[r] = y;
        }
        clean256(a, lane);
        __syncwarp();
#pragma unroll
        for (int r = 0; r < 8; r++) lists[r * 32 + lane] = a[r];
    }
    __syncthreads();
    // lists[0..255] = exact top-256 (score desc, idx asc)

    // ---- gather: 4 threads per winner; j==0 decodes box ----
    {
        int e = tid >> 2, j = tid & 3;
        u64 v = lists[e];
        unsigned kbits = (unsigned)(v >> 32);
        unsigned aidx = 0xFFFFFFFFu - (unsigned)(v & 0xFFFFFFFFu);
        const float4* row = reinterpret_cast<const float4*>(cls) +
                            ((size_t)b * A_N + aidx) * ROW4;
        float m = -INFINITY;
        int arg = 0;
#pragma unroll
        for (int q0 = 0; q0 < 5; q0++) {
            int q = j + 4 * q0;
            float4 x = row[q];
            int cc = 4 * q;
            if (x.x > m) { m = x.x; arg = cc; }
            if (x.y > m) { m = x.y; arg = cc + 1; }
            if (x.z > m) { m = x.z; arg = cc + 2; }
            if (x.w > m) { m = x.w; arg = cc + 3; }
        }
#pragma unroll
        for (int off = 1; off < 4; off <<= 1) {
            float mo = __shfl_xor_sync(0xffffffffu, m, off);
            int ao = __shfl_xor_sync(0xffffffffu, arg, off);
            if (mo > m || (mo == m && ao < arg)) { m = mo; arg = ao; }
        }
        if (j == 0) {
            sc[e] = __uint_as_float(kbits);
            lb[e] = arg;
            float4 an = reinterpret_cast<const float4*>(anchors)[aidx];
            float aw = an.z - an.x, ah = an.w - an.y;
            float acx = an.x + 0.5f * aw, acy = an.y + 0.5f * ah;
            float4 rg = reinterpret_cast<const float4*>(regs)[(size_t)b * A_N + aidx];
            float cx = acx + rg.x * aw;
            float cy = acy + rg.y * ah;
            float dw = fminf(fmaxf(rg.z, -4.0f), 4.0f);
            float dh = fminf(fmaxf(rg.w, -4.0f), 4.0f);
            float ww = aw * expf(dw);
            float hh = ah * expf(dh);
            float x1 = fminf(fmaxf(cx - 0.5f * ww, 0.0f), IMG);
            float y1 = fminf(fmaxf(cy - 0.5f * hh, 0.0f), IMG);
            float x2 = fminf(fmaxf(cx + 0.5f * ww, 0.0f), IMG);
            float y2 = fminf(fmaxf(cy + 0.5f * hh, 0.0f), IMG);
            bx[e] = make_float4(x1, y1, x2, y2);
        }
    }
    __syncthreads();

    // ---- NMS masks: 4 threads per candidate, 64 columns each ----
    {
        int i = tid >> 2, q = tid & 3;
        float4 me = bx[i];
        float myarea = fmaxf(me.z - me.x, 0.0f) * fmaxf(me.w - me.y, 0.0f);
        unsigned w0 = 0u, w1 = 0u;
        int j0 = q * 64;
#pragma unroll 4
        for (int jj = 0; jj < 64; jj++) {
            float4 o = bx[j0 + jj];
            float ix1 = fmaxf(me.x, o.x);
            float iy1 = fmaxf(me.y, o.y);
            float ix2 = fminf(me.z, o.z);
            float iy2 = fminf(me.w, o.w);
            float iw = fmaxf(ix2 - ix1, 0.0f);
            float ih = fmaxf(iy2 - iy1, 0.0f);
            float inter = iw * ih;
            float oarea = fmaxf(o.z - o.x, 0.0f) * fmaxf(o.w - o.y, 0.0f);
            float uni = myarea + oarea - inter;
            float iou = inter / fmaxf(uni, 1e-8f);
            if (iou > 0.5f) {
                if (jj < 32) w0 |= 1u << jj;
                else w1 |= 1u << (jj - 32);
            }
        }
        msk[i * 8 + q * 2 + 0] = w0;
        msk[i * 8 + q * 2 + 1] = w1;
    }
    __syncthreads();

    // ---- exact NMS in ONE warp: word-sequential outer order +
    //      register word-local Jacobi inner (no LDS/shfl chains).
    //      Unique fixpoint per word == sequential NMS result. ----
    if (w == 0) {
        unsigned fin[8];
#pragma unroll
        for (int v = 0; v < 8; v++) fin[v] = 0u;
        const unsigned below = (1u << lane) - 1u;
        for (int word = 0; word < 8; word++) {
            int c = word * 32 + lane;
            unsigned mw[8];
#pragma unroll
            for (int v = 0; v < 8; v++) mw[v] = msk[c * 8 + v];
            bool ok = sc[c] > 0.0f;
            unsigned supext = 0u;
#pragma unroll
            for (int v = 0; v < 8; v++)
                if (v < word) supext |= mw[v] & fin[v];
            bool alive = ok && (supext == 0u);
            unsigned K = __ballot_sync(0xffffffffu, alive);
            unsigned diag = mw[word] & below;   // earlier-in-word overlaps
#pragma unroll
            for (int it = 0; it < 32; it++) {
                bool sup = (diag & K) != 0u;
                unsigned K2 = __ballot_sync(0xffffffffu, alive && !sup);
                if (K2 == K) break;
                K = K2;
            }
            fin[word] = K;
        }
        if (lane < 8) keepw[lane] = fin[lane];
    }
    __syncthreads();

    // ---- output ----
    if (tid < K_N) {
        bool kp = (keepw[tid >> 5] >> (tid & 31)) & 1u;
        float kf = kp ? 1.0f : 0.0f;
        int base = b * K_N + tid;
        float4 me = bx[tid];
        out[base * 5 + 0] = me.x * kf;
        out[base * 5 + 1] = me.y * kf;
        out[base * 5 + 2] = me.z * kf;
        out[base * 5 + 3] = me.w * kf;
        out[base * 5 + 4] = sc[tid] * kf;
        if (out_size >= B_N * K_N * 5 + B_N * K_N)
            out[B_N * K_N * 5 + base] = (float)lb[tid];
        if (out_size >= B_N * K_N * 5 + 2 * B_N * K_N)
            out[B_N * K_N * 5 + B_N * K_N + base] = kf;
    }
}

// ============================================================
extern "C" void kernel_launch(void* const* d_in, const int* in_sizes, int n_in,
                              void* d_out, int out_size) {
    const float* cls = nullptr;
    const float* regs = nullptr;
    const float* anchors = nullptr;
    for (int i = 0; i < n_in; i++) {
        if (in_sizes[i] == B_N * A_N * C_N) cls = (const float*)d_in[i];
        else if (in_sizes[i] == B_N * A_N * 4) regs = (const float*)d_in[i];
        else if (in_sizes[i] == A_N * 4) anchors = (const float*)d_in[i];
    }
    if (!cls || !regs || !anchors) return;

    float* out = (float*)d_out;

    const int SMEM_K2 = 24 * 256 * sizeof(u64);   // 49152 bytes
    cudaFuncSetAttribute(k_final, cudaFuncAttributeMaxDynamicSharedMemorySize, SMEM_K2);

    k_topk_local<<<B_N * NCH, 512>>>(cls);
    k_final<<<B_N, 1024, SMEM_K2>>>(cls, regs, anchors, out, out_size);
}

// round 15
// speedup vs baseline: 1.3529x; 1.1519x over previous
#include <cuda_runtime.h>
#include <math.h>
#include <stdint.h>

#define A_N 49104
#define B_N 8
#define C_N 80
#define K_N 256
#define IMG 512.0f
#define ROW4 20                 // 80 floats = 20 float4 per anchor
#define CH 1024                 // anchors per chunk
#define NCH 48                  // chunks per batch (48*1024 >= 49104)

typedef unsigned long long u64;

// -------- device scratch --------
__device__ u64 g_cand[B_N * NCH * K_N];   // chunk top-256 lists

// ============================================================
// warp-level compare-exchange helpers (descending networks)
// ============================================================
__device__ __forceinline__ void cx_reg(u64& a, u64& b, bool desc) {
    u64 lo = (a < b) ? a : b;
    u64 hi = (a < b) ? b : a;
    a = desc ? hi : lo;
    b = desc ? lo : hi;
}
__device__ __forceinline__ u64 cx_shfl(u64 v, int j, bool desc, int lane) {
    u64 pv = __shfl_xor_sync(0xffffffffu, v, j);
    bool lower = (lane & j) == 0;
    bool keepmax = (desc == lower);
    u64 mx = (v > pv) ? v : pv;
    u64 mn = (v > pv) ? pv : v;
    return keepmax ? mx : mn;
}

// clean a 256-elem bitonic sequence (8 regs/lane, e = r*32+lane) to descending
__device__ __forceinline__ void clean256(u64 a[8], int lane) {
    cx_reg(a[0], a[4], true); cx_reg(a[1], a[5], true);
    cx_reg(a[2], a[6], true); cx_reg(a[3], a[7], true);
    cx_reg(a[0], a[2], true); cx_reg(a[1], a[3], true);
    cx_reg(a[4], a[6], true); cx_reg(a[5], a[7], true);
    cx_reg(a[0], a[1], true); cx_reg(a[2], a[3], true);
    cx_reg(a[4], a[5], true); cx_reg(a[6], a[7], true);
#pragma unroll
    for (int j = 16; j >= 1; j >>= 1)
#pragma unroll
        for (int r = 0; r < 8; r++) a[r] = cx_shfl(a[r], j, true, lane);
}

// clean a 128-elem bitonic sequence (4 regs/lane) to descending
__device__ __forceinline__ void clean128(u64 a[4], int lane) {
    cx_reg(a[0], a[2], true); cx_reg(a[1], a[3], true);
    cx_reg(a[0], a[1], true); cx_reg(a[2], a[3], true);
#pragma unroll
    for (int j = 16; j >= 1; j >>= 1)
#pragma unroll
        for (int r = 0; r < 4; r++) a[r] = cx_shfl(a[r], j, true, lane);
}

// ============================================================
// K1: fused score + chunk top-256 (unchanged from R11).
// ============================================================
__global__ __launch_bounds__(512) void k_topk_local(const float* __restrict__ cls) {
    __shared__ u64 sk[CH];
    const int tid = threadIdx.x;
    const int lane = tid & 31;
    const int w = tid >> 5;                 // warp 0..15
    const int b = blockIdx.x / NCH;
    const int c = blockIdx.x % NCH;
    const int base = c * CH + w * 64;
    const float4* cls4 = reinterpret_cast<const float4*>(cls) + (size_t)b * A_N * ROW4;

    const int j = lane & 3;
#pragma unroll
    for (int it = 0; it < 8; it++) {
        int al = it * 8 + (lane >> 2);
        int a = base + al;
        float m = -INFINITY;
        if (a < A_N) {
            const float4* row = cls4 + (size_t)a * ROW4 + j;
            float4 v0 = row[0];
            float4 v1 = row[4];
            float4 v2 = row[8];
            float4 v3 = row[12];
            float4 v4 = row[16];
            m = fmaxf(fmaxf(fmaxf(v0.x, v0.y), fmaxf(v0.z, v0.w)),
                fmaxf(fmaxf(fmaxf(v1.x, v1.y), fmaxf(v1.z, v1.w)),
                fmaxf(fmaxf(fmaxf(v2.x, v2.y), fmaxf(v2.z, v2.w)),
                fmaxf(fmaxf(fmaxf(v3.x, v3.y), fmaxf(v3.z, v3.w)),
                      fmaxf(fmaxf(v4.x, v4.y), fmaxf(v4.z, v4.w))))));
        }
        m = fmaxf(m, __shfl_xor_sync(0xffffffffu, m, 1));
        m = fmaxf(m, __shfl_xor_sync(0xffffffffu, m, 2));
        if (j == 0) {
            u64 key = 0ull;
            if (a < A_N) {
                float score = 1.0f / (1.0f + expf(-m));
                if (!(score > 0.01f)) score = 0.0f;
                key = ((u64)__float_as_uint(score) << 32) |
                      (u64)(0xFFFFFFFFu - (unsigned)a);
            }
            sk[w * 64 + al] = key;
        }
    }
    __syncwarp();

    // warp register sort of 64 keys (descending)
    {
        u64 v[2];
        v[0] = sk[w * 64 + lane];
        v[1] = sk[w * 64 + 32 + lane];
        for (int k = 2; k <= 64; k <<= 1) {
            for (int jj = k >> 1; jj >= 1; jj >>= 1) {
                if (jj >= 32) {
                    cx_reg(v[0], v[1], true);
                } else {
#pragma unroll
                    for (int r = 0; r < 2; r++) {
                        bool desc = (k >= 32) ? (((r * 32) & k) == 0)
                                              : ((lane & k) == 0);
                        v[r] = cx_shfl(v[r], jj, desc, lane);
                    }
                }
            }
        }
        sk[w * 64 + lane] = v[0];
        sk[w * 64 + 32 + lane] = v[1];
    }
    __syncthreads();

    // L1: 8 warps, full merge two 64-lists -> sorted 128
    if (w < 8) {
        int bs = w * 128;
        u64 a[4];
        a[0] = sk[bs + lane];
        a[1] = sk[bs + 32 + lane];
        a[2] = sk[bs + 64 + (63 - lane)];
        a[3] = sk[bs + 64 + (31 - lane)];
        __syncwarp();
        clean128(a, lane);
        sk[bs + lane] = a[0];
        sk[bs + 32 + lane] = a[1];
        sk[bs + 64 + lane] = a[2];
        sk[bs + 96 + lane] = a[3];
    }
    __syncthreads();

    // L2: 4 warps, full merge two 128-lists -> sorted 256
    if (w < 4) {
        int bs = w * 256;
        u64 a[8];
#pragma unroll
        for (int r = 0; r < 4; r++) a[r] = sk[bs + r * 32 + lane];
#pragma unroll
        for (int r = 4; r < 8; r++) a[r] = sk[bs + 383 - r * 32 - lane];
        __syncwarp();
        clean256(a, lane);
#pragma unroll
        for (int r = 0; r < 8; r++) sk[bs + r * 32 + lane] = a[r];
    }
    __syncthreads();

    // L3: 2 warps, truncating merge 256+256 -> top-256
    if (w < 2) {
        int A0 = w * 512;
        u64 a[8];
#pragma unroll
        for (int r = 0; r < 8; r++) {
            int e = r * 32 + lane;
            u64 x = sk[A0 + e];
            u64 y = sk[A0 + 256 + 255 - e];
            a[r] = (x > y) ? x : y;
        }
        __syncwarp();
        clean256(a, lane);
#pragma unroll
        for (int r = 0; r < 8; r++) sk[A0 + r * 32 + lane] = a[r];
    }
    __syncthreads();

    // L4: 1 warp, truncating merge -> final top-256 -> global
    if (w == 0) {
        u64 a[8];
#pragma unroll
        for (int r = 0; r < 8; r++) {
            int e = r * 32 + lane;
            u64 x = sk[e];
            u64 y = sk[512 + 255 - e];
            a[r] = (x > y) ? x : y;
        }
        clean256(a, lane);
#pragma unroll
        for (int r = 0; r < 8; r++)
            g_cand[blockIdx.x * K_N + r * 32 + lane] = a[r];
    }
}

// ============================================================
// K2: fused merge(48 lists) + gather/decode + NMS + out.
// smem overlay (u64 indices):
//   lists [0, 6144)   -- stage-1 peak; only [0,256) live after merges
//   bx    [256, 768)  -- 256 float4
//   sc    [768, 896)  -- 256 float
//   lb    [896, 1024) -- 256 int
//   msk   [1024, 2048)-- 256*8 unsigned (8KB)
//   ar    [2048, 2176)-- 256 float   (FIXED: was overlapping msk)
// ============================================================
extern __shared__ u64 sh[];

__global__ __launch_bounds__(1024) void k_final(const float* __restrict__ cls,
                                                const float* __restrict__ regs,
                                                const float* __restrict__ anchors,
                                                float* __restrict__ out,
                                                int out_size) {
    const int b = blockIdx.x;
    const int tid = threadIdx.x;
    const int lane = tid & 31;
    const int w = tid >> 5;                 // warp 0..31

    u64* lists = sh;
    float4*   bx  = reinterpret_cast<float4*>(sh + 256);
    float*    sc  = reinterpret_cast<float*>(sh + 768);
    int*      lb  = reinterpret_cast<int*>(sh + 896);
    unsigned* msk = reinterpret_cast<unsigned*>(sh + 1024); // 8KB
    float*    ar  = reinterpret_cast<float*>(sh + 2048);    // past msk
    __shared__ unsigned keepw[8];

    u64 a[8];

    // ---- stage 1: 24 warps: trunc-merge g_cand pairs -> lists[w] ----
    if (w < 24) {
        const u64* A = g_cand + ((size_t)(b * NCH + 2 * w)) * K_N;
        const u64* B = A + K_N;
#pragma unroll
        for (int r = 0; r < 8; r++) {
            int e = r * 32 + lane;
            u64 x = A[e], y = B[255 - e];
            a[r] = (x > y) ? x : y;
        }
        clean256(a, lane);
#pragma unroll
        for (int r = 0; r < 8; r++) lists[w * 256 + r * 32 + lane] = a[r];
    }
    __syncthreads();

    // ---- stages 2-4: 12, 6, 3 active warps ----
#pragma unroll
    for (int npair = 12; npair >= 3; npair >>= 1) {
        if (w < npair) {
#pragma unroll
            for (int r = 0; r < 8; r++) {
                int e = r * 32 + lane;
                u64 x = lists[2 * w * 256 + e];
                u64 y = lists[(2 * w + 1) * 256 + 255 - e];
                a[r] = (x > y) ? x : y;
            }
        }
        __syncthreads();
        if (w < npair) {
            clean256(a, lane);
#pragma unroll
            for (int r = 0; r < 8; r++) lists[w * 256 + r * 32 + lane] = a[r];
        }
        __syncthreads();
    }

    // ---- final: warp 0 chains lists 0,1 then 2 ----
    if (w == 0) {
#pragma unroll
        for (int r = 0; r < 8; r++) {
            int e = r * 32 + lane;
            u64 x = lists[e];
            u64 y = lists[256 + 255 - e];
            a[r] = (x > y) ? x : y;
        }
        clean256(a, lane);
#pragma unroll
        for (int r = 0; r < 8; r++) {
            int e = r * 32 + lane;
            u64 y = lists[512 + 255 - e];
            if (y > a[r]) a[r] = y;
        }
        clean256(a, lane);
        __syncwarp();
#pragma unroll
        for (int r = 0; r < 8; r++) lists[r * 32 + lane] = a[r];
    }
    __syncthreads();
    // lists[0..255] = exact top-256 (score desc, idx asc)

    // ---- gather: 4 threads per winner; j==0 decodes box ----
    {
        int e = tid >> 2, j = tid & 3;
        u64 v = lists[e];
        unsigned kbits = (unsigned)(v >> 32);
        unsigned aidx = 0xFFFFFFFFu - (unsigned)(v & 0xFFFFFFFFu);
        const float4* row = reinterpret_cast<const float4*>(cls) +
                            ((size_t)b * A_N + aidx) * ROW4;
        float m = -INFINITY;
        int arg = 0;
#pragma unroll
        for (int q0 = 0; q0 < 5; q0++) {
            int q = j + 4 * q0;
            float4 x = row[q];
            int cc = 4 * q;
            if (x.x > m) { m = x.x; arg = cc; }
            if (x.y > m) { m = x.y; arg = cc + 1; }
            if (x.z > m) { m = x.z; arg = cc + 2; }
            if (x.w > m) { m = x.w; arg = cc + 3; }
        }
#pragma unroll
        for (int off = 1; off < 4; off <<= 1) {
            float mo = __shfl_xor_sync(0xffffffffu, m, off);
            int ao = __shfl_xor_sync(0xffffffffu, arg, off);
            if (mo > m || (mo == m && ao < arg)) { m = mo; arg = ao; }
        }
        if (j == 0) {
            sc[e] = __uint_as_float(kbits);
            lb[e] = arg;
            float4 an = reinterpret_cast<const float4*>(anchors)[aidx];
            float aw = an.z - an.x, ah = an.w - an.y;
            float acx = an.x + 0.5f * aw, acy = an.y + 0.5f * ah;
            float4 rg = reinterpret_cast<const float4*>(regs)[(size_t)b * A_N + aidx];
            float cx = acx + rg.x * aw;
            float cy = acy + rg.y * ah;
            float dw = fminf(fmaxf(rg.z, -4.0f), 4.0f);
            float dh = fminf(fmaxf(rg.w, -4.0f), 4.0f);
            float ww = aw * expf(dw);
            float hh = ah * expf(dh);
            float x1 = fminf(fmaxf(cx - 0.5f * ww, 0.0f), IMG);
            float y1 = fminf(fmaxf(cy - 0.5f * hh, 0.0f), IMG);
            float x2 = fminf(fmaxf(cx + 0.5f * ww, 0.0f), IMG);
            float y2 = fminf(fmaxf(cy + 0.5f * hh, 0.0f), IMG);
            bx[e] = make_float4(x1, y1, x2, y2);
        }
    }
    __syncthreads();

    // ---- precompute areas (threads 0..255) ----
    if (tid < K_N) {
        float4 o = bx[tid];
        ar[tid] = fmaxf(o.z - o.x, 0.0f) * fmaxf(o.w - o.y, 0.0f);
    }
    __syncthreads();

    // ---- NMS masks (TRIANGULAR: only j < i), division-free ----
    // suppress(i,j) <=> iou>0.5 <=> inter > 0.5*max(uni,1e-8)
    {
        int i = tid >> 2, q = tid & 3;
        float4 me = bx[i];
        float myarea = ar[i];
        unsigned w0 = 0u, w1 = 0u;
        int j0 = q * 64;
        int bound = i - j0;
        if (bound > 64) bound = 64;
        for (int jj = 0; jj < bound; jj++) {
            float4 o = bx[j0 + jj];
            float ix1 = fmaxf(me.x, o.x);
            float iy1 = fmaxf(me.y, o.y);
            float ix2 = fminf(me.z, o.z);
            float iy2 = fminf(me.w, o.w);
            float iw = fmaxf(ix2 - ix1, 0.0f);
            float ih = fmaxf(iy2 - iy1, 0.0f);
            float inter = iw * ih;
            float uni = myarea + ar[j0 + jj] - inter;
            if (inter > 0.5f * fmaxf(uni, 1e-8f)) {
                if (jj < 32) w0 |= 1u << jj;
                else w1 |= 1u << (jj - 32);
            }
        }
        msk[i * 8 + q * 2 + 0] = w0;
        msk[i * 8 + q * 2 + 1] = w1;
    }
    __syncthreads();

    // ---- exact NMS in ONE warp: word-sequential outer order +
    //      register word-local Jacobi inner (R13, proven fast) ----
    if (w == 0) {
        unsigned fin[8];
#pragma unroll
        for (int v = 0; v < 8; v++) fin[v] = 0u;
        const unsigned below = (1u << lane) - 1u;
        for (int word = 0; word < 8; word++) {
            int c = word * 32 + lane;
            unsigned mw[8];
#pragma unroll
            for (int v = 0; v < 8; v++) mw[v] = msk[c * 8 + v];
            bool ok = sc[c] > 0.0f;
            unsigned supext = 0u;
#pragma unroll
            for (int v = 0; v < 8; v++)
                if (v < word) supext |= mw[v] & fin[v];
            bool alive = ok && (supext == 0u);
            unsigned K = __ballot_sync(0xffffffffu, alive);
            unsigned diag = mw[word] & below;
#pragma unroll
            for (int it = 0; it < 32; it++) {
                bool sup = (diag & K) != 0u;
                unsigned K2 = __ballot_sync(0xffffffffu, alive && !sup);
                if (K2 == K) break;
                K = K2;
            }
            fin[word] = K;
        }
        if (lane < 8) keepw[lane] = fin[lane];
    }
    __syncthreads();

    // ---- output ----
    if (tid < K_N) {
        bool kp = (keepw[tid >> 5] >> (tid & 31)) & 1u;
        float kf = kp ? 1.0f : 0.0f;
        int base = b * K_N + tid;
        float4 me = bx[tid];
        out[base * 5 + 0] = me.x * kf;
        out[base * 5 + 1] = me.y * kf;
        out[base * 5 + 2] = me.z * kf;
        out[base * 5 + 3] = me.w * kf;
        out[base * 5 + 4] = sc[tid] * kf;
        if (out_size >= B_N * K_N * 5 + B_N * K_N)
            out[B_N * K_N * 5 + base] = (float)lb[tid];
        if (out_size >= B_N * K_N * 5 + 2 * B_N * K_N)
            out[B_N * K_N * 5 + B_N * K_N + base] = kf;
    }
}

// ============================================================
extern "C" void kernel_launch(void* const* d_in, const int* in_sizes, int n_in,
                              void* d_out, int out_size) {
    const float* cls = nullptr;
    const float* regs = nullptr;
    const float* anchors = nullptr;
    for (int i = 0; i < n_in; i++) {
        if (in_sizes[i] == B_N * A_N * C_N) cls = (const float*)d_in[i];
        else if (in_sizes[i] == B_N * A_N * 4) regs = (const float*)d_in[i];
        else if (in_sizes[i] == A_N * 4) anchors = (const float*)d_in[i];
    }
    if (!cls || !regs || !anchors) return;

    float* out = (float*)d_out;

    const int SMEM_K2 = 24 * 256 * sizeof(u64);   // 49152 bytes
    cudaFuncSetAttribute(k_final, cudaFuncAttributeMaxDynamicSharedMemorySize, SMEM_K2);

    k_topk_local<<<B_N * NCH, 512>>>(cls);
    k_final<<<B_N, 1024, SMEM_K2>>>(cls, regs, anchors, out, out_size);
}

// round 16
// speedup vs baseline: 1.3830x; 1.0223x over previous
#include <cuda_runtime.h>
#include <math.h>
#include <stdint.h>

#define A_N 49104
#define B_N 8
#define C_N 80
#define K_N 256
#define IMG 512.0f
#define ROW4 20                 // 80 floats = 20 float4 per anchor
#define CH 1024                 // anchors per chunk
#define NCH 48                  // chunks per batch (48*1024 >= 49104)
#define TOTAL (B_N * A_N)

typedef unsigned long long u64;

// -------- device scratch --------
__device__ u64 g_cand[B_N * NCH * K_N];       // chunk top-256 lists
__device__ u64 g_oct [B_N * 4 * K_N];         // 12-way premerged lists
__device__ unsigned char g_lab[TOTAL];        // per-anchor argmax label

// ============================================================
// warp-level compare-exchange helpers (descending networks)
// ============================================================
__device__ __forceinline__ void cx_reg(u64& a, u64& b, bool desc) {
    u64 lo = (a < b) ? a : b;
    u64 hi = (a < b) ? b : a;
    a = desc ? hi : lo;
    b = desc ? lo : hi;
}
__device__ __forceinline__ u64 cx_shfl(u64 v, int j, bool desc, int lane) {
    u64 pv = __shfl_xor_sync(0xffffffffu, v, j);
    bool lower = (lane & j) == 0;
    bool keepmax = (desc == lower);
    u64 mx = (v > pv) ? v : pv;
    u64 mn = (v > pv) ? pv : v;
    return keepmax ? mx : mn;
}

// clean a 256-elem bitonic sequence (8 regs/lane) to descending
__device__ __forceinline__ void clean256(u64 a[8], int lane) {
    cx_reg(a[0], a[4], true); cx_reg(a[1], a[5], true);
    cx_reg(a[2], a[6], true); cx_reg(a[3], a[7], true);
    cx_reg(a[0], a[2], true); cx_reg(a[1], a[3], true);
    cx_reg(a[4], a[6], true); cx_reg(a[5], a[7], true);
    cx_reg(a[0], a[1], true); cx_reg(a[2], a[3], true);
    cx_reg(a[4], a[5], true); cx_reg(a[6], a[7], true);
#pragma unroll
    for (int j = 16; j >= 1; j >>= 1)
#pragma unroll
        for (int r = 0; r < 8; r++) a[r] = cx_shfl(a[r], j, true, lane);
}

// clean a 128-elem bitonic sequence (4 regs/lane) to descending
__device__ __forceinline__ void clean128(u64 a[4], int lane) {
    cx_reg(a[0], a[2], true); cx_reg(a[1], a[3], true);
    cx_reg(a[0], a[1], true); cx_reg(a[2], a[3], true);
#pragma unroll
    for (int j = 16; j >= 1; j >>= 1)
#pragma unroll
        for (int r = 0; r < 4; r++) a[r] = cx_shfl(a[r], j, true, lane);
}

// ============================================================
// K1: fused score + argmax label + chunk top-256.
// ============================================================
__global__ __launch_bounds__(512) void k_topk_local(const float* __restrict__ cls) {
    __shared__ u64 sk[CH];
    const int tid = threadIdx.x;
    const int lane = tid & 31;
    const int w = tid >> 5;                 // warp 0..15
    const int b = blockIdx.x / NCH;
    const int c = blockIdx.x % NCH;
    const int base = c * CH + w * 64;
    const float4* cls4 = reinterpret_cast<const float4*>(cls) + (size_t)b * A_N * ROW4;

    const int j = lane & 3;
#pragma unroll
    for (int it = 0; it < 8; it++) {
        int al = it * 8 + (lane >> 2);
        int a = base + al;
        float m = -INFINITY;
        int arg = 0;
        if (a < A_N) {
            const float4* row = cls4 + (size_t)a * ROW4 + j;
#pragma unroll
            for (int i = 0; i < 5; i++) {
                float4 v = row[i * 4];
                int cc = 16 * i + 4 * j;     // class of v.x for f4 index j+4i
                if (v.x > m) { m = v.x; arg = cc; }
                if (v.y > m) { m = v.y; arg = cc + 1; }
                if (v.z > m) { m = v.z; arg = cc + 2; }
                if (v.w > m) { m = v.w; arg = cc + 3; }
            }
        }
        // 4-lane max+argmax reduce (lowest class index on ties)
#pragma unroll
        for (int off = 1; off < 4; off <<= 1) {
            float mo = __shfl_xor_sync(0xffffffffu, m, off);
            int ao = __shfl_xor_sync(0xffffffffu, arg, off);
            if (mo > m || (mo == m && ao < arg)) { m = mo; arg = ao; }
        }
        if (j == 0) {
            u64 key = 0ull;
            if (a < A_N) {
                float score = 1.0f / (1.0f + expf(-m));
                if (!(score > 0.01f)) score = 0.0f;
                key = ((u64)__float_as_uint(score) << 32) |
                      (u64)(0xFFFFFFFFu - (unsigned)a);
                g_lab[(size_t)b * A_N + a] = (unsigned char)arg;
            }
            sk[w * 64 + al] = key;
        }
    }
    __syncwarp();

    // warp register sort of 64 keys (descending)
    {
        u64 v[2];
        v[0] = sk[w * 64 + lane];
        v[1] = sk[w * 64 + 32 + lane];
        for (int k = 2; k <= 64; k <<= 1) {
            for (int jj = k >> 1; jj >= 1; jj >>= 1) {
                if (jj >= 32) {
                    cx_reg(v[0], v[1], true);
                } else {
#pragma unroll
                    for (int r = 0; r < 2; r++) {
                        bool desc = (k >= 32) ? (((r * 32) & k) == 0)
                                              : ((lane & k) == 0);
                        v[r] = cx_shfl(v[r], jj, desc, lane);
                    }
                }
            }
        }
        sk[w * 64 + lane] = v[0];
        sk[w * 64 + 32 + lane] = v[1];
    }
    __syncthreads();

    // L1: 8 warps, full merge two 64-lists -> sorted 128
    if (w < 8) {
        int bs = w * 128;
        u64 a[4];
        a[0] = sk[bs + lane];
        a[1] = sk[bs + 32 + lane];
        a[2] = sk[bs + 64 + (63 - lane)];
        a[3] = sk[bs + 64 + (31 - lane)];
        __syncwarp();
        clean128(a, lane);
        sk[bs + lane] = a[0];
        sk[bs + 32 + lane] = a[1];
        sk[bs + 64 + lane] = a[2];
        sk[bs + 96 + lane] = a[3];
    }
    __syncthreads();

    // L2: 4 warps, full merge two 128-lists -> sorted 256
    if (w < 4) {
        int bs = w * 256;
        u64 a[8];
#pragma unroll
        for (int r = 0; r < 4; r++) a[r] = sk[bs + r * 32 + lane];
#pragma unroll
        for (int r = 4; r < 8; r++) a[r] = sk[bs + 383 - r * 32 - lane];
        __syncwarp();
        clean256(a, lane);
#pragma unroll
        for (int r = 0; r < 8; r++) sk[bs + r * 32 + lane] = a[r];
    }
    __syncthreads();

    // L3: 2 warps, truncating merge 256+256 -> top-256
    if (w < 2) {
        int A0 = w * 512;
        u64 a[8];
#pragma unroll
        for (int r = 0; r < 8; r++) {
            int e = r * 32 + lane;
            u64 x = sk[A0 + e];
            u64 y = sk[A0 + 256 + 255 - e];
            a[r] = (x > y) ? x : y;
        }
        __syncwarp();
        clean256(a, lane);
#pragma unroll
        for (int r = 0; r < 8; r++) sk[A0 + r * 32 + lane] = a[r];
    }
    __syncthreads();

    // L4: 1 warp, truncating merge -> final top-256 -> global
    if (w == 0) {
        u64 a[8];
#pragma unroll
        for (int r = 0; r < 8; r++) {
            int e = r * 32 + lane;
            u64 x = sk[e];
            u64 y = sk[512 + 255 - e];
            a[r] = (x > y) ? x : y;
        }
        clean256(a, lane);
#pragma unroll
        for (int r = 0; r < 8; r++)
            g_cand[blockIdx.x * K_N + r * 32 + lane] = a[r];
    }
}

// ============================================================
// K2a: premerge 12 chunk-lists -> one top-256. grid = B_N*4.
// ============================================================
__global__ __launch_bounds__(512) void k_premerge() {
    __shared__ u64 ls[6 * 256];
    const int tid = threadIdx.x;
    const int lane = tid & 31;
    const int w = tid >> 5;                 // warp 0..15
    const int b = blockIdx.x >> 2;
    const int o = blockIdx.x & 3;
    const u64* src = g_cand + ((size_t)(b * NCH + o * 12)) * K_N;

    u64 a[8];

    // stage A: warps 0..5 trunc-merge pairs (2w, 2w+1) -> ls[w]
    if (w < 6) {
        const u64* A = src + (2 * w) * K_N;
        const u64* B = A + K_N;
#pragma unroll
        for (int r = 0; r < 8; r++) {
            int e = r * 32 + lane;
            u64 x = A[e], y = B[255 - e];
            a[r] = (x > y) ? x : y;
        }
        clean256(a, lane);
#pragma unroll
        for (int r = 0; r < 8; r++) ls[w * 256 + r * 32 + lane] = a[r];
    }
    __syncthreads();

    // stage B: warps 0..2 merge (ls[2w], ls[2w+1]) -> ls[w]
    if (w < 3) {
#pragma unroll
        for (int r = 0; r < 8; r++) {
            int e = r * 32 + lane;
            u64 x = ls[2 * w * 256 + e];
            u64 y = ls[(2 * w + 1) * 256 + 255 - e];
            a[r] = (x > y) ? x : y;
        }
    }
    __syncthreads();
    if (w < 3) {
        clean256(a, lane);
#pragma unroll
        for (int r = 0; r < 8; r++) ls[w * 256 + r * 32 + lane] = a[r];
    }
    __syncthreads();

    // stage C: warp 0 chains ls0+ls1 then +ls2 -> g_oct
    if (w == 0) {
#pragma unroll
        for (int r = 0; r < 8; r++) {
            int e = r * 32 + lane;
            u64 x = ls[e];
            u64 y = ls[256 + 255 - e];
            a[r] = (x > y) ? x : y;
        }
        clean256(a, lane);
#pragma unroll
        for (int r = 0; r < 8; r++) {
            int e = r * 32 + lane;
            u64 y = ls[512 + 255 - e];
            if (y > a[r]) a[r] = y;
        }
        clean256(a, lane);
#pragma unroll
        for (int r = 0; r < 8; r++)
            g_oct[(size_t)blockIdx.x * K_N + r * 32 + lane] = a[r];
    }
}

// ============================================================
// K2b: merge 4 lists + light gather + NMS + output. grid = B_N.
// ============================================================
__global__ __launch_bounds__(1024) void k_final(const float* __restrict__ regs,
                                                const float* __restrict__ anchors,
                                                float* __restrict__ out,
                                                int out_size) {
    const int b = blockIdx.x;
    const int tid = threadIdx.x;
    const int lane = tid & 31;
    const int w = tid >> 5;                 // warp 0..31

    __shared__ u64 ls[512];
    __shared__ u64 topk[K_N];
    __shared__ float4 bxs[K_N];
    __shared__ float scs[K_N];
    __shared__ int lbs[K_N];
    __shared__ unsigned msks[K_N * 8];
    __shared__ float ars[K_N];
    __shared__ unsigned keepw[8];

    u64 a[8];

    // stage 1: warps 0,1 trunc-merge g_oct pairs -> ls[w]
    if (w < 2) {
        const u64* A = g_oct + ((size_t)(b * 4 + 2 * w)) * K_N;
        const u64* B = A + K_N;
#pragma unroll
        for (int r = 0; r < 8; r++) {
            int e = r * 32 + lane;
            u64 x = A[e], y = B[255 - e];
            a[r] = (x > y) ? x : y;
        }
        clean256(a, lane);
#pragma unroll
        for (int r = 0; r < 8; r++) ls[w * 256 + r * 32 + lane] = a[r];
    }
    __syncthreads();

    // stage 2: warp 0 merges ls0, ls1 -> topk
    if (w == 0) {
#pragma unroll
        for (int r = 0; r < 8; r++) {
            int e = r * 32 + lane;
            u64 x = ls[e];
            u64 y = ls[256 + 255 - e];
            a[r] = (x > y) ? x : y;
        }
        clean256(a, lane);
#pragma unroll
        for (int r = 0; r < 8; r++) topk[r * 32 + lane] = a[r];
    }
    __syncthreads();
    // topk[0..255] = exact top-256 (score desc, idx asc)

    // light gather: 1 thread per winner (label precomputed in K1)
    if (tid < K_N) {
        u64 v = topk[tid];
        unsigned kbits = (unsigned)(v >> 32);
        unsigned aidx = 0xFFFFFFFFu - (unsigned)(v & 0xFFFFFFFFu);
        scs[tid] = __uint_as_float(kbits);
        lbs[tid] = (int)g_lab[(size_t)b * A_N + aidx];
        float4 an = reinterpret_cast<const float4*>(anchors)[aidx];
        float aw = an.z - an.x, ah = an.w - an.y;
        float acx = an.x + 0.5f * aw, acy = an.y + 0.5f * ah;
        float4 rg = reinterpret_cast<const float4*>(regs)[(size_t)b * A_N + aidx];
        float cx = acx + rg.x * aw;
        float cy = acy + rg.y * ah;
        float dw = fminf(fmaxf(rg.z, -4.0f), 4.0f);
        float dh = fminf(fmaxf(rg.w, -4.0f), 4.0f);
        float ww = aw * expf(dw);
        float hh = ah * expf(dh);
        float x1 = fminf(fmaxf(cx - 0.5f * ww, 0.0f), IMG);
        float y1 = fminf(fmaxf(cy - 0.5f * hh, 0.0f), IMG);
        float x2 = fminf(fmaxf(cx + 0.5f * ww, 0.0f), IMG);
        float y2 = fminf(fmaxf(cy + 0.5f * hh, 0.0f), IMG);
        bxs[tid] = make_float4(x1, y1, x2, y2);
        ars[tid] = fmaxf(x2 - x1, 0.0f) * fmaxf(y2 - y1, 0.0f);
    }
    __syncthreads();

    // NMS masks (triangular j<i), division-free: iou>0.5 <=> inter > 0.5*max(uni,1e-8)
    {
        int i = tid >> 2, q = tid & 3;
        float4 me = bxs[i];
        float myarea = ars[i];
        unsigned w0 = 0u, w1 = 0u;
        int j0 = q * 64;
        int bound = i - j0;
        if (bound > 64) bound = 64;
        for (int jj = 0; jj < bound; jj++) {
            float4 o = bxs[j0 + jj];
            float ix1 = fmaxf(me.x, o.x);
            float iy1 = fmaxf(me.y, o.y);
            float ix2 = fminf(me.z, o.z);
            float iy2 = fminf(me.w, o.w);
            float iw = fmaxf(ix2 - ix1, 0.0f);
            float ih = fmaxf(iy2 - iy1, 0.0f);
            float inter = iw * ih;
            float uni = myarea + ars[j0 + jj] - inter;
            if (inter > 0.5f * fmaxf(uni, 1e-8f)) {
                if (jj < 32) w0 |= 1u << jj;
                else w1 |= 1u << (jj - 32);
            }
        }
        msks[i * 8 + q * 2 + 0] = w0;
        msks[i * 8 + q * 2 + 1] = w1;
    }
    __syncthreads();

    // exact NMS in ONE warp: word-sequential outer + word-local Jacobi inner
    if (w == 0) {
        unsigned fin[8];
#pragma unroll
        for (int v = 0; v < 8; v++) fin[v] = 0u;
        const unsigned below = (1u << lane) - 1u;
        for (int word = 0; word < 8; word++) {
            int c = word * 32 + lane;
            unsigned mw[8];
#pragma unroll
            for (int v = 0; v < 8; v++) mw[v] = msks[c * 8 + v];
            bool ok = scs[c] > 0.0f;
            unsigned supext = 0u;
#pragma unroll
            for (int v = 0; v < 8; v++)
                if (v < word) supext |= mw[v] & fin[v];
            bool alive = ok && (supext == 0u);
            unsigned K = __ballot_sync(0xffffffffu, alive);
            unsigned diag = mw[word] & below;
#pragma unroll
            for (int it = 0; it < 32; it++) {
                bool sup = (diag & K) != 0u;
                unsigned K2 = __ballot_sync(0xffffffffu, alive && !sup);
                if (K2 == K) break;
                K = K2;
            }
            fin[word] = K;
        }
        if (lane < 8) keepw[lane] = fin[lane];
    }
    __syncthreads();

    // output
    if (tid < K_N) {
        bool kp = (keepw[tid >> 5] >> (tid & 31)) & 1u;
        float kf = kp ? 1.0f : 0.0f;
        int base = b * K_N + tid;
        float4 me = bxs[tid];
        out[base * 5 + 0] = me.x * kf;
        out[base * 5 + 1] = me.y * kf;
        out[base * 5 + 2] = me.z * kf;
        out[base * 5 + 3] = me.w * kf;
        out[base * 5 + 4] = scs[tid] * kf;
        if (out_size >= B_N * K_N * 5 + B_N * K_N)
            out[B_N * K_N * 5 + base] = (float)lbs[tid];
        if (out_size >= B_N * K_N * 5 + 2 * B_N * K_N)
            out[B_N * K_N * 5 + B_N * K_N + base] = kf;
    }
}

// ============================================================
extern "C" void kernel_launch(void* const* d_in, const int* in_sizes, int n_in,
                              void* d_out, int out_size) {
    const float* cls = nullptr;
    const float* regs = nullptr;
    const float* anchors = nullptr;
    for (int i = 0; i < n_in; i++) {
        if (in_sizes[i] == B_N * A_N * C_N) cls = (const float*)d_in[i];
        else if (in_sizes[i] == B_N * A_N * 4) regs = (const float*)d_in[i];
        else if (in_sizes[i] == A_N * 4) anchors = (const float*)d_in[i];
    }
    if (!cls || !regs || !anchors) return;

    float* out = (float*)d_out;

    k_topk_local<<<B_N * NCH, 512>>>(cls);
    k_premerge<<<B_N * 4, 512>>>();
    k_final<<<B_N, 1024>>>(regs, anchors, out, out_size);
}

// round 17
// speedup vs baseline: 1.4431x; 1.0435x over previous
#include <cuda_runtime.h>
#include <math.h>
#include <stdint.h>

#define A_N 49104
#define B_N 8
#define C_N 80
#define K_N 256
#define IMG 512.0f
#define ROW4 20                 // 80 floats = 20 float4 per anchor
#define CH 1024                 // anchors per chunk
#define NCH 48                  // chunks per batch (48*1024 >= 49104)

typedef unsigned long long u64;

// -------- device scratch --------
__device__ u64 g_cand[B_N * NCH * K_N];       // chunk top-256 lists
__device__ u64 g_oct [B_N * 4 * K_N];         // 12-way premerged lists

// ============================================================
// warp-level compare-exchange helpers (descending networks)
// ============================================================
__device__ __forceinline__ void cx_reg(u64& a, u64& b, bool desc) {
    u64 lo = (a < b) ? a : b;
    u64 hi = (a < b) ? b : a;
    a = desc ? hi : lo;
    b = desc ? lo : hi;
}
__device__ __forceinline__ u64 cx_shfl(u64 v, int j, bool desc, int lane) {
    u64 pv = __shfl_xor_sync(0xffffffffu, v, j);
    bool lower = (lane & j) == 0;
    bool keepmax = (desc == lower);
    u64 mx = (v > pv) ? v : pv;
    u64 mn = (v > pv) ? pv : v;
    return keepmax ? mx : mn;
}

// clean a 256-elem bitonic sequence (8 regs/lane) to descending
__device__ __forceinline__ void clean256(u64 a[8], int lane) {
    cx_reg(a[0], a[4], true); cx_reg(a[1], a[5], true);
    cx_reg(a[2], a[6], true); cx_reg(a[3], a[7], true);
    cx_reg(a[0], a[2], true); cx_reg(a[1], a[3], true);
    cx_reg(a[4], a[6], true); cx_reg(a[5], a[7], true);
    cx_reg(a[0], a[1], true); cx_reg(a[2], a[3], true);
    cx_reg(a[4], a[5], true); cx_reg(a[6], a[7], true);
#pragma unroll
    for (int j = 16; j >= 1; j >>= 1)
#pragma unroll
        for (int r = 0; r < 8; r++) a[r] = cx_shfl(a[r], j, true, lane);
}

// clean a 128-elem bitonic sequence (4 regs/lane) to descending
__device__ __forceinline__ void clean128(u64 a[4], int lane) {
    cx_reg(a[0], a[2], true); cx_reg(a[1], a[3], true);
    cx_reg(a[0], a[1], true); cx_reg(a[2], a[3], true);
#pragma unroll
    for (int j = 16; j >= 1; j >>= 1)
#pragma unroll
        for (int r = 0; r < 4; r++) a[r] = cx_shfl(a[r], j, true, lane);
}

// ============================================================
// K1: fused score + chunk top-256 (max-only, R15-proven config).
// ============================================================
__global__ __launch_bounds__(512) void k_topk_local(const float* __restrict__ cls) {
    __shared__ u64 sk[CH];
    const int tid = threadIdx.x;
    const int lane = tid & 31;
    const int w = tid >> 5;                 // warp 0..15
    const int b = blockIdx.x / NCH;
    const int c = blockIdx.x % NCH;
    const int base = c * CH + w * 64;
    const float4* cls4 = reinterpret_cast<const float4*>(cls) + (size_t)b * A_N * ROW4;

    const int j = lane & 3;
#pragma unroll
    for (int it = 0; it < 8; it++) {
        int al = it * 8 + (lane >> 2);
        int a = base + al;
        float m = -INFINITY;
        if (a < A_N) {
            const float4* row = cls4 + (size_t)a * ROW4 + j;
            float4 v0 = row[0];
            float4 v1 = row[4];
            float4 v2 = row[8];
            float4 v3 = row[12];
            float4 v4 = row[16];
            m = fmaxf(fmaxf(fmaxf(v0.x, v0.y), fmaxf(v0.z, v0.w)),
                fmaxf(fmaxf(fmaxf(v1.x, v1.y), fmaxf(v1.z, v1.w)),
                fmaxf(fmaxf(fmaxf(v2.x, v2.y), fmaxf(v2.z, v2.w)),
                fmaxf(fmaxf(fmaxf(v3.x, v3.y), fmaxf(v3.z, v3.w)),
                      fmaxf(fmaxf(v4.x, v4.y), fmaxf(v4.z, v4.w))))));
        }
        m = fmaxf(m, __shfl_xor_sync(0xffffffffu, m, 1));
        m = fmaxf(m, __shfl_xor_sync(0xffffffffu, m, 2));
        if (j == 0) {
            u64 key = 0ull;
            if (a < A_N) {
                float score = 1.0f / (1.0f + expf(-m));
                if (!(score > 0.01f)) score = 0.0f;
                key = ((u64)__float_as_uint(score) << 32) |
                      (u64)(0xFFFFFFFFu - (unsigned)a);
            }
            sk[w * 64 + al] = key;
        }
    }
    __syncwarp();

    // warp register sort of 64 keys (descending)
    {
        u64 v[2];
        v[0] = sk[w * 64 + lane];
        v[1] = sk[w * 64 + 32 + lane];
        for (int k = 2; k <= 64; k <<= 1) {
            for (int jj = k >> 1; jj >= 1; jj >>= 1) {
                if (jj >= 32) {
                    cx_reg(v[0], v[1], true);
                } else {
#pragma unroll
                    for (int r = 0; r < 2; r++) {
                        bool desc = (k >= 32) ? (((r * 32) & k) == 0)
                                              : ((lane & k) == 0);
                        v[r] = cx_shfl(v[r], jj, desc, lane);
                    }
                }
            }
        }
        sk[w * 64 + lane] = v[0];
        sk[w * 64 + 32 + lane] = v[1];
    }
    __syncthreads();

    // L1: 8 warps, full merge two 64-lists -> sorted 128
    if (w < 8) {
        int bs = w * 128;
        u64 a[4];
        a[0] = sk[bs + lane];
        a[1] = sk[bs + 32 + lane];
        a[2] = sk[bs + 64 + (63 - lane)];
        a[3] = sk[bs + 64 + (31 - lane)];
        __syncwarp();
        clean128(a, lane);
        sk[bs + lane] = a[0];
        sk[bs + 32 + lane] = a[1];
        sk[bs + 64 + lane] = a[2];
        sk[bs + 96 + lane] = a[3];
    }
    __syncthreads();

    // L2: 4 warps, full merge two 128-lists -> sorted 256
    if (w < 4) {
        int bs = w * 256;
        u64 a[8];
#pragma unroll
        for (int r = 0; r < 4; r++) a[r] = sk[bs + r * 32 + lane];
#pragma unroll
        for (int r = 4; r < 8; r++) a[r] = sk[bs + 383 - r * 32 - lane];
        __syncwarp();
        clean256(a, lane);
#pragma unroll
        for (int r = 0; r < 8; r++) sk[bs + r * 32 + lane] = a[r];
    }
    __syncthreads();

    // L3: 2 warps, truncating merge 256+256 -> top-256
    if (w < 2) {
        int A0 = w * 512;
        u64 a[8];
#pragma unroll
        for (int r = 0; r < 8; r++) {
            int e = r * 32 + lane;
            u64 x = sk[A0 + e];
            u64 y = sk[A0 + 256 + 255 - e];
            a[r] = (x > y) ? x : y;
        }
        __syncwarp();
        clean256(a, lane);
#pragma unroll
        for (int r = 0; r < 8; r++) sk[A0 + r * 32 + lane] = a[r];
    }
    __syncthreads();

    // L4: 1 warp, truncating merge -> final top-256 -> global
    if (w == 0) {
        u64 a[8];
#pragma unroll
        for (int r = 0; r < 8; r++) {
            int e = r * 32 + lane;
            u64 x = sk[e];
            u64 y = sk[512 + 255 - e];
            a[r] = (x > y) ? x : y;
        }
        clean256(a, lane);
#pragma unroll
        for (int r = 0; r < 8; r++)
            g_cand[blockIdx.x * K_N + r * 32 + lane] = a[r];
    }
}

// ============================================================
// K2a: premerge 12 chunk-lists -> one top-256. grid = B_N*4.
// ============================================================
__global__ __launch_bounds__(512) void k_premerge() {
    __shared__ u64 ls[6 * 256];
    const int tid = threadIdx.x;
    const int lane = tid & 31;
    const int w = tid >> 5;
    const int b = blockIdx.x >> 2;
    const int o = blockIdx.x & 3;
    const u64* src = g_cand + ((size_t)(b * NCH + o * 12)) * K_N;

    u64 a[8];

    // stage A: warps 0..5 trunc-merge pairs (2w, 2w+1) -> ls[w]
    if (w < 6) {
        const u64* A = src + (2 * w) * K_N;
        const u64* B = A + K_N;
#pragma unroll
        for (int r = 0; r < 8; r++) {
            int e = r * 32 + lane;
            u64 x = A[e], y = B[255 - e];
            a[r] = (x > y) ? x : y;
        }
        clean256(a, lane);
#pragma unroll
        for (int r = 0; r < 8; r++) ls[w * 256 + r * 32 + lane] = a[r];
    }
    __syncthreads();

    // stage B: warps 0..2 merge (ls[2w], ls[2w+1]) -> ls[w]
    if (w < 3) {
#pragma unroll
        for (int r = 0; r < 8; r++) {
            int e = r * 32 + lane;
            u64 x = ls[2 * w * 256 + e];
            u64 y = ls[(2 * w + 1) * 256 + 255 - e];
            a[r] = (x > y) ? x : y;
        }
    }
    __syncthreads();
    if (w < 3) {
        clean256(a, lane);
#pragma unroll
        for (int r = 0; r < 8; r++) ls[w * 256 + r * 32 + lane] = a[r];
    }
    __syncthreads();

    // stage C: warp 0 chains ls0+ls1 then +ls2 -> g_oct
    if (w == 0) {
#pragma unroll
        for (int r = 0; r < 8; r++) {
            int e = r * 32 + lane;
            u64 x = ls[e];
            u64 y = ls[256 + 255 - e];
            a[r] = (x > y) ? x : y;
        }
        clean256(a, lane);
#pragma unroll
        for (int r = 0; r < 8; r++) {
            int e = r * 32 + lane;
            u64 y = ls[512 + 255 - e];
            if (y > a[r]) a[r] = y;
        }
        clean256(a, lane);
#pragma unroll
        for (int r = 0; r < 8; r++)
            g_oct[(size_t)blockIdx.x * K_N + r * 32 + lane] = a[r];
    }
}

// ============================================================
// K2b: merge 4 lists + gather (4-thr argmax) + NMS + output.
// ============================================================
__global__ __launch_bounds__(1024) void k_final(const float* __restrict__ cls,
                                                const float* __restrict__ regs,
                                                const float* __restrict__ anchors,
                                                float* __restrict__ out,
                                                int out_size) {
    const int b = blockIdx.x;
    const int tid = threadIdx.x;
    const int lane = tid & 31;
    const int w = tid >> 5;

    __shared__ u64 ls[512];
    __shared__ u64 topk[K_N];
    __shared__ float4 bxs[K_N];
    __shared__ float scs[K_N];
    __shared__ int lbs[K_N];
    __shared__ unsigned msks[K_N * 8];
    __shared__ float ars[K_N];
    __shared__ unsigned keepw[8];

    u64 a[8];

    // stage 1: warps 0,1 trunc-merge g_oct pairs -> ls[w]
    if (w < 2) {
        const u64* A = g_oct + ((size_t)(b * 4 + 2 * w)) * K_N;
        const u64* B = A + K_N;
#pragma unroll
        for (int r = 0; r < 8; r++) {
            int e = r * 32 + lane;
            u64 x = A[e], y = B[255 - e];
            a[r] = (x > y) ? x : y;
        }
        clean256(a, lane);
#pragma unroll
        for (int r = 0; r < 8; r++) ls[w * 256 + r * 32 + lane] = a[r];
    }
    __syncthreads();

    // stage 2: warp 0 merges ls0, ls1 -> topk
    if (w == 0) {
#pragma unroll
        for (int r = 0; r < 8; r++) {
            int e = r * 32 + lane;
            u64 x = ls[e];
            u64 y = ls[256 + 255 - e];
            a[r] = (x > y) ? x : y;
        }
        clean256(a, lane);
#pragma unroll
        for (int r = 0; r < 8; r++) topk[r * 32 + lane] = a[r];
    }
    __syncthreads();
    // topk[0..255] = exact top-256 (score desc, idx asc)

    // gather: 4 threads per winner recompute argmax; j==0 decodes box
    {
        int e = tid >> 2, j = tid & 3;
        u64 v = topk[e];
        unsigned kbits = (unsigned)(v >> 32);
        unsigned aidx = 0xFFFFFFFFu - (unsigned)(v & 0xFFFFFFFFu);
        const float4* row = reinterpret_cast<const float4*>(cls) +
                            ((size_t)b * A_N + aidx) * ROW4;
        float m = -INFINITY;
        int arg = 0;
#pragma unroll
        for (int q0 = 0; q0 < 5; q0++) {
            int q = j + 4 * q0;
            float4 x = row[q];
            int cc = 4 * q;
            if (x.x > m) { m = x.x; arg = cc; }
            if (x.y > m) { m = x.y; arg = cc + 1; }
            if (x.z > m) { m = x.z; arg = cc + 2; }
            if (x.w > m) { m = x.w; arg = cc + 3; }
        }
#pragma unroll
        for (int off = 1; off < 4; off <<= 1) {
            float mo = __shfl_xor_sync(0xffffffffu, m, off);
            int ao = __shfl_xor_sync(0xffffffffu, arg, off);
            if (mo > m || (mo == m && ao < arg)) { m = mo; arg = ao; }
        }
        if (j == 0) {
            scs[e] = __uint_as_float(kbits);
            lbs[e] = arg;
            float4 an = reinterpret_cast<const float4*>(anchors)[aidx];
            float aw = an.z - an.x, ah = an.w - an.y;
            float acx = an.x + 0.5f * aw, acy = an.y + 0.5f * ah;
            float4 rg = reinterpret_cast<const float4*>(regs)[(size_t)b * A_N + aidx];
            float cx = acx + rg.x * aw;
            float cy = acy + rg.y * ah;
            float dw = fminf(fmaxf(rg.z, -4.0f), 4.0f);
            float dh = fminf(fmaxf(rg.w, -4.0f), 4.0f);
            float ww = aw * expf(dw);
            float hh = ah * expf(dh);
            float x1 = fminf(fmaxf(cx - 0.5f * ww, 0.0f), IMG);
            float y1 = fminf(fmaxf(cy - 0.5f * hh, 0.0f), IMG);
            float x2 = fminf(fmaxf(cx + 0.5f * ww, 0.0f), IMG);
            float y2 = fminf(fmaxf(cy + 0.5f * hh, 0.0f), IMG);
            bxs[e] = make_float4(x1, y1, x2, y2);
            ars[e] = fmaxf(x2 - x1, 0.0f) * fmaxf(y2 - y1, 0.0f);
        }
    }
    __syncthreads();

    // NMS masks (triangular j<i), division-free
    {
        int i = tid >> 2, q = tid & 3;
        float4 me = bxs[i];
        float myarea = ars[i];
        unsigned w0 = 0u, w1 = 0u;
        int j0 = q * 64;
        int bound = i - j0;
        if (bound > 64) bound = 64;
        for (int jj = 0; jj < bound; jj++) {
            float4 o = bxs[j0 + jj];
            float ix1 = fmaxf(me.x, o.x);
            float iy1 = fmaxf(me.y, o.y);
            float ix2 = fminf(me.z, o.z);
            float iy2 = fminf(me.w, o.w);
            float iw = fmaxf(ix2 - ix1, 0.0f);
            float ih = fmaxf(iy2 - iy1, 0.0f);
            float inter = iw * ih;
            float uni = myarea + ars[j0 + jj] - inter;
            if (inter > 0.5f * fmaxf(uni, 1e-8f)) {
                if (jj < 32) w0 |= 1u << jj;
                else w1 |= 1u << (jj - 32);
            }
        }
        msks[i * 8 + q * 2 + 0] = w0;
        msks[i * 8 + q * 2 + 1] = w1;
    }
    __syncthreads();

    // exact NMS in ONE warp: word-sequential outer + word-local Jacobi inner
    if (w == 0) {
        unsigned fin[8];
#pragma unroll
        for (int v = 0; v < 8; v++) fin[v] = 0u;
        const unsigned below = (1u << lane) - 1u;
        for (int word = 0; word < 8; word++) {
            int c = word * 32 + lane;
            unsigned mw[8];
#pragma unroll
            for (int v = 0; v < 8; v++) mw[v] = msks[c * 8 + v];
            bool ok = scs[c] > 0.0f;
            unsigned supext = 0u;
#pragma unroll
            for (int v = 0; v < 8; v++)
                if (v < word) supext |= mw[v] & fin[v];
            bool alive = ok && (supext == 0u);
            unsigned K = __ballot_sync(0xffffffffu, alive);
            unsigned diag = mw[word] & below;
#pragma unroll
            for (int it = 0; it < 32; it++) {
                bool sup = (diag & K) != 0u;
                unsigned K2 = __ballot_sync(0xffffffffu, alive && !sup);
                if (K2 == K) break;
                K = K2;
            }
            fin[word] = K;
        }
        if (lane < 8) keepw[lane] = fin[lane];
    }
    __syncthreads();

    // output
    if (tid < K_N) {
        bool kp = (keepw[tid >> 5] >> (tid & 31)) & 1u;
        float kf = kp ? 1.0f : 0.0f;
        int base = b * K_N + tid;
        float4 me = bxs[tid];
        out[base * 5 + 0] = me.x * kf;
        out[base * 5 + 1] = me.y * kf;
        out[base * 5 + 2] = me.z * kf;
        out[base * 5 + 3] = me.w * kf;
        out[base * 5 + 4] = scs[tid] * kf;
        if (out_size >= B_N * K_N * 5 + B_N * K_N)
            out[B_N * K_N * 5 + base] = (float)lbs[tid];
        if (out_size >= B_N * K_N * 5 + 2 * B_N * K_N)
            out[B_N * K_N * 5 + B_N * K_N + base] = kf;
    }
}

// ============================================================
extern "C" void kernel_launch(void* const* d_in, const int* in_sizes, int n_in,
                              void* d_out, int out_size) {
    const float* cls = nullptr;
    const float* regs = nullptr;
    const float* anchors = nullptr;
    for (int i = 0; i < n_in; i++) {
        if (in_sizes[i] == B_N * A_N * C_N) cls = (const float*)d_in[i];
        else if (in_sizes[i] == B_N * A_N * 4) regs = (const float*)d_in[i];
        else if (in_sizes[i] == A_N * 4) anchors = (const float*)d_in[i];
    }
    if (!cls || !regs || !anchors) return;

    float* out = (float*)d_out;

    k_topk_local<<<B_N * NCH, 512>>>(cls);
    k_premerge<<<B_N * 4, 512>>>();
    k_final<<<B_N, 1024>>>(cls, regs, anchors, out, out_size);
}